// round 14
// baseline (speedup 1.0000x reference)
#include <cuda_runtime.h>
#include <cstdint>

// NoiseLinear: out[b,o] = sum_i x[b,i]*w[o,i]*(1 + 0.1*eps[b,o,i]) + bias[o]
// eps = jax.random.normal(key(seed), (B,OUT,IN)) — partitionable threefry.
// R14 = R13 (790.7us) + ONLY the mad.hi.u32 prelude fusion:
// (bits>>9)+0x3f800000 -> one IMAD.HI on the FMA pipe (opaque 2^23 multiplier
// so ptxas can't strength-reduce back to SHF+IADD). Bit-identical transform.

#define B_DIM  64
#define IN_DIM 1024
#define OUT_DIM 4096

// Opaque 2^23 so ptxas can't strength-reduce mad.hi back to SHF+IADD.
__device__ uint32_t g_m23 = 1u << 23;

// ---- packed f32x2 helpers ----
#define PACK2(out, lo, hi) \
    asm("mov.b64 %0, {%1, %2};" : "=l"(out) : "f"(lo), "f"(hi))
#define UNPACK2(lo, hi, in) \
    asm("mov.b64 {%0, %1}, %2;" : "=f"(lo), "=f"(hi) : "l"(in))
#define FMA2(d, a, b, c) \
    asm("fma.rn.f32x2 %0, %1, %2, %3;" : "=l"(d) : "l"(a), "l"(b), "l"(c))
#define ADD2(d, a, b) \
    asm("add.rn.f32x2 %0, %1, %2;" : "=l"(d) : "l"(a), "l"(b))
#define MUL2(d, a, b) \
    asm("mul.rn.f32x2 %0, %1, %2;" : "=l"(d) : "l"(a), "l"(b))

__device__ __forceinline__ uint64_t bcast2(float c) {
    uint32_t b = __float_as_uint(c);
    return ((uint64_t)b << 32) | (uint64_t)b;
}

// Full 20-round threefry2x32, key (0, seed); returns o0 ^ o1.
// c1k = counter + ks1 (pre-folded). Plain SHF rotates (proven optimal;
// R2/R9 showed any pipe substitution in the cipher loses to exposed latency).
__device__ __forceinline__ uint32_t tf2x32_bits(uint32_t ks1, uint32_t ks2,
                                                uint32_t c1k) {
    uint32_t x0, x1 = c1k;
    x0 = x1;                                    // round 1 add (x0_init = 0)
    x1 = __funnelshift_l(x1, x1, 13); x1 ^= x0;
#define TF_R(r) { x0 += x1; x1 = __funnelshift_l(x1, x1, (r)); x1 ^= x0; }
    TF_R(15) TF_R(26) TF_R(6)
    x0 += ks1;      x1 += ks2 + 1u;
    TF_R(17) TF_R(29) TF_R(16) TF_R(24)
    x0 += ks2;      x1 += 2u;                   // + ks0(=0) + 2
    TF_R(13) TF_R(15) TF_R(26) TF_R(6)
    /* x0 += ks0 */ x1 += ks1 + 3u;
    TF_R(17) TF_R(29) TF_R(16) TF_R(24)
    x0 += ks1;      x1 += ks2 + 4u;
    TF_R(13) TF_R(15) TF_R(26) TF_R(6)
    x0 += ks2;      x1 += 5u;                   // + ks0(=0) + 5
#undef TF_R
    return x0 ^ x1;
}

// Scalar prelude: bits -> (u, L).  (bits>>9)+0x3f800000 fused into one
// mad.hi.u32 ((bits*2^23)>>32 == bits>>9 exactly). Clamp kept: u=-1 at
// bits>>9==0 (expected ~32 times over 268M samples) must match JAX's clamp.
__device__ __forceinline__ void prelude(uint32_t bits, uint32_t m23,
                                        float& u, float& L) {
    uint32_t vb;
    asm("mad.hi.u32 %0, %1, %2, %3;"
        : "=r"(vb) : "r"(bits), "r"(m23), "r"(0x3f800000u));
    float v = __uint_as_float(vb);                          // [1,2)
    u = __fmaf_rn(v, 2.0f, -3.0f);                          // ~[-1,1)
    u = fmaxf(u, -0.99999994f);                             // keep 1-u^2 > 0
    float t = __fmaf_rn(u, -u, 1.0f);                       // (0,1]
    L = __log2f(t);
}

// Cheap rare-tail (w = -ln(1-u^2) >= 6): first-order erfc asymptotic.
__device__ __forceinline__ float cheap_tail(float L) {
    float w  = __fmul_rn(L, -0.69314718f);
    float t1 = __fadd_rn(w, 0.12078223f);
    float g  = __log2f(w);
    float y2 = __fmaf_rn(g, -0.34657359f, t1);
    float y  = __fsqrt_rn(y2);
    return __fmul_rn(y, 0.14166f);                  // 0.1*sqrt(2)*1.0017
}

#define TAIL_TH (-8.6561702f)   /* -6/ln2 : w >= 6 */

// One warp per (b-quad, o). b-quad = bp, bp+16, bp+32, bp+48; bp in [0,16).
__global__ void __launch_bounds__(256, 3)
noise_linear_kernel(const float* __restrict__ x, const float* __restrict__ w,
                    const float* __restrict__ bias, const int* __restrict__ seedp,
                    float* __restrict__ out) {
    const uint32_t ks1 = (uint32_t)seedp[0];
    const uint32_t ks2 = ks1 ^ 0x1BD11BDAu;
    const uint32_t m23 = *(volatile const uint32_t*)&g_m23;

    // packed central-poly coefficients (0.1*sqrt(2) folded; s-domain,
    // s = log2(1-u^2) + 2.5/ln2)
    const uint64_t C8 = bcast2(2.1176117e-10f);
    const uint64_t C7 = bcast2(-3.7320261e-09f);
    const uint64_t C6 = bcast2(-5.5262276e-08f);
    const uint64_t C5 = bcast2(9.9370005e-08f);
    const uint64_t C4 = bcast2(7.1355326e-06f);
    const uint64_t C3 = bcast2(5.9044926e-05f);
    const uint64_t C2 = bcast2(-2.8386012e-04f);
    const uint64_t C1 = bcast2(-2.4177344e-02f);
    const uint64_t C0 = bcast2(2.1233136e-01f);
    const uint64_t SK = bcast2(3.6067376f);          // +2.5/ln2
    const uint64_t ONE2 = bcast2(1.0f);

    const int gw   = blockIdx.x * (blockDim.x >> 5) + (threadIdx.x >> 5);
    const int lane = threadIdx.x & 31;
    const int o  = gw & (OUT_DIM - 1);
    const int bp = gw >> 12;                 // 0..15

    const float4* __restrict__ wrow  = (const float4*)(w + (size_t)o * IN_DIM);
    const float4* __restrict__ x0row = (const float4*)(x + (size_t)(bp     ) * IN_DIM);
    const float4* __restrict__ x1row = (const float4*)(x + (size_t)(bp + 16) * IN_DIM);
    const float4* __restrict__ x2row = (const float4*)(x + (size_t)(bp + 32) * IN_DIM);
    const float4* __restrict__ x3row = (const float4*)(x + (size_t)(bp + 48) * IN_DIM);

    const uint32_t bk0 = (uint32_t)bp * (OUT_DIM * IN_DIM)
                       + (uint32_t)o * IN_DIM + ks1;
    const uint32_t RS = 16u * OUT_DIM * IN_DIM;

    uint64_t accA = 0, accB = 0;             // packed accumulators

#pragma unroll 1
    for (int ii = 0; ii < IN_DIM / 128; ++ii) {     // 8 iterations
        const int vec = ii * 32 + lane;
        const float4 w4 = __ldg(wrow  + vec);
        const float4 a4 = __ldg(x0row + vec);
        const float4 b4 = __ldg(x1row + vec);
        const float4 c4 = __ldg(x2row + vec);
        const float4 d4 = __ldg(x3row + vec);
        const uint32_t cb = bk0 + (uint32_t)vec * 4u;
#pragma unroll
        for (int j = 0; j < 4; ++j) {
            const float wv = (&w4.x)[j];
            const uint32_t ci = cb + (uint32_t)j;

            // packed t = wv * xrow
            uint64_t WV2, abA, abB, tA, tB;
            PACK2(WV2, wv, wv);
            PACK2(abA, (&a4.x)[j], (&b4.x)[j]);
            PACK2(abB, (&c4.x)[j], (&d4.x)[j]);
            MUL2(tA, WV2, abA);
            MUL2(tB, WV2, abB);

            const uint32_t bits0 = tf2x32_bits(ks1, ks2, ci);
            const uint32_t bits1 = tf2x32_bits(ks1, ks2, ci + RS);
            const uint32_t bits2 = tf2x32_bits(ks1, ks2, ci + 2u * RS);
            const uint32_t bits3 = tf2x32_bits(ks1, ks2, ci + 3u * RS);

            float u0, L0, u1, L1, u2, L2, u3, L3;
            prelude(bits0, m23, u0, L0);
            prelude(bits1, m23, u1, L1);
            prelude(bits2, m23, u2, L2);
            prelude(bits3, m23, u3, L3);

            // packed s = L + 2.5/ln2, then packed Horner (p stays packed)
            uint64_t LA, LB, sA, sB, pA, pB;
            PACK2(LA, L0, L1);
            PACK2(LB, L2, L3);
            ADD2(sA, LA, SK);
            ADD2(sB, LB, SK);
            FMA2(pA, C8, sA, C7);   FMA2(pB, C8, sB, C7);
            FMA2(pA, pA, sA, C6);   FMA2(pB, pB, sB, C6);
            FMA2(pA, pA, sA, C5);   FMA2(pB, pB, sB, C5);
            FMA2(pA, pA, sA, C4);   FMA2(pB, pB, sB, C4);
            FMA2(pA, pA, sA, C3);   FMA2(pB, pB, sB, C3);
            FMA2(pA, pA, sA, C2);   FMA2(pB, pB, sB, C2);
            FMA2(pA, pA, sA, C1);   FMA2(pB, pB, sB, C1);
            FMA2(pA, pA, sA, C0);   FMA2(pB, pB, sB, C0);

            // combined rare-tail gate (w >= 6; warp-any ~14.7%)
            const float Lmin = fminf(fminf(L0, L1), fminf(L2, L3));
            if (__any_sync(0xFFFFFFFFu, Lmin <= TAIL_TH)) {
                float p0, p1, p2, p3;
                UNPACK2(p0, p1, pA);
                UNPACK2(p2, p3, pB);
                p0 = (L0 <= TAIL_TH) ? cheap_tail(L0) : p0;
                p1 = (L1 <= TAIL_TH) ? cheap_tail(L1) : p1;
                p2 = (L2 <= TAIL_TH) ? cheap_tail(L2) : p2;
                p3 = (L3 <= TAIL_TH) ? cheap_tail(L3) : p3;
                PACK2(pA, p0, p1);
                PACK2(pB, p2, p3);
            }

            // packed m = 1 + 0.1*eps; packed accumulate
            uint64_t uA, uB, mA, mB;
            PACK2(uA, u0, u1);
            PACK2(uB, u2, u3);
            FMA2(mA, pA, uA, ONE2);
            FMA2(mB, pB, uB, ONE2);
            FMA2(accA, mA, tA, accA);
            FMA2(accB, mB, tB, accB);
        }
    }

    // unpack accumulators, warp butterfly reduce
    float acc0, acc1, acc2, acc3;
    UNPACK2(acc0, acc1, accA);
    UNPACK2(acc2, acc3, accB);
#pragma unroll
    for (int off = 16; off > 0; off >>= 1) {
        acc0 += __shfl_xor_sync(0xFFFFFFFFu, acc0, off);
        acc1 += __shfl_xor_sync(0xFFFFFFFFu, acc1, off);
        acc2 += __shfl_xor_sync(0xFFFFFFFFu, acc2, off);
        acc3 += __shfl_xor_sync(0xFFFFFFFFu, acc3, off);
    }

    if (lane == 0) {
        const float bz = __ldg(bias + o);
        out[(size_t)(bp     ) * OUT_DIM + o] = acc0 + bz;
        out[(size_t)(bp + 16) * OUT_DIM + o] = acc1 + bz;
        out[(size_t)(bp + 32) * OUT_DIM + o] = acc2 + bz;
        out[(size_t)(bp + 48) * OUT_DIM + o] = acc3 + bz;
    }
}

extern "C" void kernel_launch(void* const* d_in, const int* in_sizes, int n_in,
                              void* d_out, int out_size) {
    const float* x    = (const float*)d_in[0];
    const float* w    = (const float*)d_in[1];
    const float* bias = (const float*)d_in[2];
    const int*   seed = (const int*)d_in[3];
    float* out = (float*)d_out;

    // 16 b-quads * 4096 outputs = 65536 warps; 8 warps/block -> 8192 blocks
    noise_linear_kernel<<<8192, 256>>>(x, w, bias, seed, out);
}

// round 15
// speedup vs baseline: 1.0449x; 1.0449x over previous
#include <cuda_runtime.h>
#include <cstdint>

// NoiseLinear: out[b,o] = sum_i x[b,i]*w[o,i]*(1 + 0.1*eps[b,o,i]) + bias[o]
// eps = jax.random.normal(key(seed), (B,OUT,IN)) — partitionable threefry.
// R15 = R13 (790.7us; R14's mad.hi prelude reverted — 3rd failed IMAD
// substitution, lesson is final) + two chain-neutral slot shaves:
// (a) u-clamp removed from the hot path; the 1-in-2^23 bits>>9==0 samples
//     give L=-inf, always hit the tail gate, and a w-clamp INSIDE the rare
//     path (w=min(w,15.9424)) reproduces JAX's clamped value exactly.
// (b) tail threshold w>=6 -> w>=7 (gate-taken warp-prob 14.7% -> 5.7%;
//     central-poly extrapolation err over [6,7] diluted to ~1e-5 in out).

#define B_DIM  64
#define IN_DIM 1024
#define OUT_DIM 4096

// ---- packed f32x2 helpers ----
#define PACK2(out, lo, hi) \
    asm("mov.b64 %0, {%1, %2};" : "=l"(out) : "f"(lo), "f"(hi))
#define UNPACK2(lo, hi, in) \
    asm("mov.b64 {%0, %1}, %2;" : "=f"(lo), "=f"(hi) : "l"(in))
#define FMA2(d, a, b, c) \
    asm("fma.rn.f32x2 %0, %1, %2, %3;" : "=l"(d) : "l"(a), "l"(b), "l"(c))
#define ADD2(d, a, b) \
    asm("add.rn.f32x2 %0, %1, %2;" : "=l"(d) : "l"(a), "l"(b))
#define MUL2(d, a, b) \
    asm("mul.rn.f32x2 %0, %1, %2;" : "=l"(d) : "l"(a), "l"(b))

__device__ __forceinline__ uint64_t bcast2(float c) {
    uint32_t b = __float_as_uint(c);
    return ((uint64_t)b << 32) | (uint64_t)b;
}

// Full 20-round threefry2x32, key (0, seed); returns o0 ^ o1.
// c1k = counter + ks1 (pre-folded). Plain SHF rotates — proven optimal
// (R2/R9/R14: every IMAD-family substitution lost to schedule/latency).
__device__ __forceinline__ uint32_t tf2x32_bits(uint32_t ks1, uint32_t ks2,
                                                uint32_t c1k) {
    uint32_t x0, x1 = c1k;
    x0 = x1;                                    // round 1 add (x0_init = 0)
    x1 = __funnelshift_l(x1, x1, 13); x1 ^= x0;
#define TF_R(r) { x0 += x1; x1 = __funnelshift_l(x1, x1, (r)); x1 ^= x0; }
    TF_R(15) TF_R(26) TF_R(6)
    x0 += ks1;      x1 += ks2 + 1u;
    TF_R(17) TF_R(29) TF_R(16) TF_R(24)
    x0 += ks2;      x1 += 2u;                   // + ks0(=0) + 2
    TF_R(13) TF_R(15) TF_R(26) TF_R(6)
    /* x0 += ks0 */ x1 += ks1 + 3u;
    TF_R(17) TF_R(29) TF_R(16) TF_R(24)
    x0 += ks1;      x1 += ks2 + 4u;
    TF_R(13) TF_R(15) TF_R(26) TF_R(6)
    x0 += ks2;      x1 += 5u;                   // + ks0(=0) + 5
#undef TF_R
    return x0 ^ x1;
}

// Scalar prelude: bits -> (u, L). NO u-clamp: u = -1 exactly only when
// bits>>9 == 0 (L = -inf), which always takes the tail path where w is
// clamped to match JAX's u-clamp. Chain is one FMNMX shorter.
__device__ __forceinline__ void prelude(uint32_t bits, float& u, float& L) {
    float v = __uint_as_float((bits >> 9) + 0x3f800000u);   // [1,2)
    u = __fmaf_rn(v, 2.0f, -3.0f);                          // [-1,1)
    float t = __fmaf_rn(u, -u, 1.0f);                       // [0,1]
    L = __log2f(t);                                         // -inf at u=-1
}

// Cheap rare-tail (w = -ln(1-u^2) >= 7): first-order erfc asymptotic.
// w clamped at 15.9424 = -ln(2^-23): reproduces JAX's u-clamp for the
// bits>>9==0 samples (L=-inf -> w=inf -> clamp).
__device__ __forceinline__ float cheap_tail(float L) {
    float w  = __fmul_rn(L, -0.69314718f);
    w = fminf(w, 15.9424f);
    float t1 = __fadd_rn(w, 0.12078223f);
    float g  = __log2f(w);
    float y2 = __fmaf_rn(g, -0.34657359f, t1);
    float y  = __fsqrt_rn(y2);
    return __fmul_rn(y, 0.14166f);                  // 0.1*sqrt(2)*1.0017
}

#define TAIL_TH (-10.0988655f)   /* -7/ln2 : w >= 7 */

// One warp per (b-quad, o). b-quad = bp, bp+16, bp+32, bp+48; bp in [0,16).
__global__ void __launch_bounds__(256, 3)
noise_linear_kernel(const float* __restrict__ x, const float* __restrict__ w,
                    const float* __restrict__ bias, const int* __restrict__ seedp,
                    float* __restrict__ out) {
    const uint32_t ks1 = (uint32_t)seedp[0];
    const uint32_t ks2 = ks1 ^ 0x1BD11BDAu;

    // packed central-poly coefficients (0.1*sqrt(2) folded; s-domain,
    // s = log2(1-u^2) + 2.5/ln2)
    const uint64_t C8 = bcast2(2.1176117e-10f);
    const uint64_t C7 = bcast2(-3.7320261e-09f);
    const uint64_t C6 = bcast2(-5.5262276e-08f);
    const uint64_t C5 = bcast2(9.9370005e-08f);
    const uint64_t C4 = bcast2(7.1355326e-06f);
    const uint64_t C3 = bcast2(5.9044926e-05f);
    const uint64_t C2 = bcast2(-2.8386012e-04f);
    const uint64_t C1 = bcast2(-2.4177344e-02f);
    const uint64_t C0 = bcast2(2.1233136e-01f);
    const uint64_t SK = bcast2(3.6067376f);          // +2.5/ln2
    const uint64_t ONE2 = bcast2(1.0f);

    const int gw   = blockIdx.x * (blockDim.x >> 5) + (threadIdx.x >> 5);
    const int lane = threadIdx.x & 31;
    const int o  = gw & (OUT_DIM - 1);
    const int bp = gw >> 12;                 // 0..15

    const float4* __restrict__ wrow  = (const float4*)(w + (size_t)o * IN_DIM);
    const float4* __restrict__ x0row = (const float4*)(x + (size_t)(bp     ) * IN_DIM);
    const float4* __restrict__ x1row = (const float4*)(x + (size_t)(bp + 16) * IN_DIM);
    const float4* __restrict__ x2row = (const float4*)(x + (size_t)(bp + 32) * IN_DIM);
    const float4* __restrict__ x3row = (const float4*)(x + (size_t)(bp + 48) * IN_DIM);

    const uint32_t bk0 = (uint32_t)bp * (OUT_DIM * IN_DIM)
                       + (uint32_t)o * IN_DIM + ks1;
    const uint32_t RS = 16u * OUT_DIM * IN_DIM;

    uint64_t accA = 0, accB = 0;             // packed accumulators

#pragma unroll 1
    for (int ii = 0; ii < IN_DIM / 128; ++ii) {     // 8 iterations
        const int vec = ii * 32 + lane;
        const float4 w4 = __ldg(wrow  + vec);
        const float4 a4 = __ldg(x0row + vec);
        const float4 b4 = __ldg(x1row + vec);
        const float4 c4 = __ldg(x2row + vec);
        const float4 d4 = __ldg(x3row + vec);
        const uint32_t cb = bk0 + (uint32_t)vec * 4u;
#pragma unroll
        for (int j = 0; j < 4; ++j) {
            const float wv = (&w4.x)[j];
            const uint32_t ci = cb + (uint32_t)j;

            // packed t = wv * xrow
            uint64_t WV2, abA, abB, tA, tB;
            PACK2(WV2, wv, wv);
            PACK2(abA, (&a4.x)[j], (&b4.x)[j]);
            PACK2(abB, (&c4.x)[j], (&d4.x)[j]);
            MUL2(tA, WV2, abA);
            MUL2(tB, WV2, abB);

            const uint32_t bits0 = tf2x32_bits(ks1, ks2, ci);
            const uint32_t bits1 = tf2x32_bits(ks1, ks2, ci + RS);
            const uint32_t bits2 = tf2x32_bits(ks1, ks2, ci + 2u * RS);
            const uint32_t bits3 = tf2x32_bits(ks1, ks2, ci + 3u * RS);

            float u0, L0, u1, L1, u2, L2, u3, L3;
            prelude(bits0, u0, L0);
            prelude(bits1, u1, L1);
            prelude(bits2, u2, L2);
            prelude(bits3, u3, L3);

            // packed s = L + 2.5/ln2, then packed Horner (p stays packed)
            uint64_t LA, LB, sA, sB, pA, pB;
            PACK2(LA, L0, L1);
            PACK2(LB, L2, L3);
            ADD2(sA, LA, SK);
            ADD2(sB, LB, SK);
            FMA2(pA, C8, sA, C7);   FMA2(pB, C8, sB, C7);
            FMA2(pA, pA, sA, C6);   FMA2(pB, pB, sB, C6);
            FMA2(pA, pA, sA, C5);   FMA2(pB, pB, sB, C5);
            FMA2(pA, pA, sA, C4);   FMA2(pB, pB, sB, C4);
            FMA2(pA, pA, sA, C3);   FMA2(pB, pB, sB, C3);
            FMA2(pA, pA, sA, C2);   FMA2(pB, pB, sB, C2);
            FMA2(pA, pA, sA, C1);   FMA2(pB, pB, sB, C1);
            FMA2(pA, pA, sA, C0);   FMA2(pB, pB, sB, C0);

            // combined rare-tail gate (w >= 7; warp-any ~5.7%).
            // L=-inf (the unclamped u=-1 samples) always lands here.
            const float Lmin = fminf(fminf(L0, L1), fminf(L2, L3));
            if (__any_sync(0xFFFFFFFFu, Lmin <= TAIL_TH)) {
                float p0, p1, p2, p3;
                UNPACK2(p0, p1, pA);
                UNPACK2(p2, p3, pB);
                p0 = (L0 <= TAIL_TH) ? cheap_tail(L0) : p0;
                p1 = (L1 <= TAIL_TH) ? cheap_tail(L1) : p1;
                p2 = (L2 <= TAIL_TH) ? cheap_tail(L2) : p2;
                p3 = (L3 <= TAIL_TH) ? cheap_tail(L3) : p3;
                PACK2(pA, p0, p1);
                PACK2(pB, p2, p3);
            }

            // packed m = 1 + 0.1*eps; packed accumulate
            uint64_t uA, uB, mA, mB;
            PACK2(uA, u0, u1);
            PACK2(uB, u2, u3);
            FMA2(mA, pA, uA, ONE2);
            FMA2(mB, pB, uB, ONE2);
            FMA2(accA, mA, tA, accA);
            FMA2(accB, mB, tB, accB);
        }
    }

    // unpack accumulators, warp butterfly reduce
    float acc0, acc1, acc2, acc3;
    UNPACK2(acc0, acc1, accA);
    UNPACK2(acc2, acc3, accB);
#pragma unroll
    for (int off = 16; off > 0; off >>= 1) {
        acc0 += __shfl_xor_sync(0xFFFFFFFFu, acc0, off);
        acc1 += __shfl_xor_sync(0xFFFFFFFFu, acc1, off);
        acc2 += __shfl_xor_sync(0xFFFFFFFFu, acc2, off);
        acc3 += __shfl_xor_sync(0xFFFFFFFFu, acc3, off);
    }

    if (lane == 0) {
        const float bz = __ldg(bias + o);
        out[(size_t)(bp     ) * OUT_DIM + o] = acc0 + bz;
        out[(size_t)(bp + 16) * OUT_DIM + o] = acc1 + bz;
        out[(size_t)(bp + 32) * OUT_DIM + o] = acc2 + bz;
        out[(size_t)(bp + 48) * OUT_DIM + o] = acc3 + bz;
    }
}

extern "C" void kernel_launch(void* const* d_in, const int* in_sizes, int n_in,
                              void* d_out, int out_size) {
    const float* x    = (const float*)d_in[0];
    const float* w    = (const float*)d_in[1];
    const float* bias = (const float*)d_in[2];
    const int*   seed = (const int*)d_in[3];
    float* out = (float*)d_out;

    // 16 b-quads * 4096 outputs = 65536 warps; 8 warps/block -> 8192 blocks
    noise_linear_kernel<<<8192, 256>>>(x, w, bias, seed, out);
}